// round 14
// baseline (speedup 1.0000x reference)
#include <cuda_runtime.h>
#include <cuda_bf16.h>
#include <stdint.h>
#include <math.h>

#define NN    4096
#define DIN   768
#define CD    128
#define HH1   4
#define F1    512
#define CHUNK 256
#define NCH   (NN/CHUNK)   // 16 (passA chunks)
#define SC    512          // sort chunk size
#define NSC   8            // sort chunks
#define BK1   32           // mma gemm K-chunk
#define NCH1  (DIN/BK1)    // 24 (layer1); layer2 uses F1/BK1 = 16
#define TSTR  40           // smem row stride in bf16 elems (80B) -> conflict-free frags
#define TILEB (128*TSTR*2) // 10240 B per tile

typedef unsigned long long ull;

// ---------------- device scratch (no allocs allowed) ----------------
__device__ float g_h1[NN*F1];
__device__ float g_h2[NN*CD];
__device__ float g_x2[NN*CD];

__device__ __nv_bfloat16 g_XH[NN*DIN],  g_XL[NN*DIN];     // split X
__device__ __nv_bfloat16 g_BtH[F1*DIN], g_BtL[F1*DIN];    // split W1^T [512][768]
__device__ __nv_bfloat16 g_x1H[NN*F1],  g_x1L[NN*F1];     // split x1 (layer2 A)
__device__ __nv_bfloat16 g_Bt2H[CD*F1], g_Bt2L[CD*F1];    // split W2^T [128][512]

__device__ float g_s1[HH1*NN], g_t1[HH1*NN], g_ss1[HH1*NN];
__device__ float g_w0_1[HH1*NN], g_w1_1[HH1*NN], g_z0_1[HH1*NN], g_z1_1[HH1*NN];
__device__ int   g_si1[HH1*NN];
__device__ int   g_k1[HH1*NN];
__device__ float2 g_a1[HH1*NN];
__device__ float g_I0_1[HH1*NN*CD], g_S1_1[HH1*NN*CD];
__device__ float g_O0_1[HH1*NCH*CD], g_O1_1[HH1*NCH*CD];

__device__ float g_s2[NN], g_t2[NN], g_ss2[NN];
__device__ float g_w0_2[NN], g_w1_2[NN], g_z0_2[NN], g_z1_2[NN];
__device__ int   g_si2[NN];
__device__ int   g_k2[NN];
__device__ float2 g_a2[NN];
__device__ float g_I0_2[NN*CD], g_S1_2[NN*CD];
__device__ float g_O0_2[NCH*CD], g_O1_2[NCH*CD];

__device__ ull   g_sc[HH1*NN];

__device__ float g_part[32*CD];

// ---------------- helpers ----------------
__device__ __forceinline__ float elu1(float x) { return x > 0.f ? x : expm1f(x); }

// mma.sync bf16 (sm_80+ ISA; compiles on compute_103 base target)
__device__ __forceinline__ void mma_bf16(float* c, const uint32_t* a, const uint32_t* b) {
    asm volatile(
        "mma.sync.aligned.m16n8k16.row.col.f32.bf16.bf16.f32 "
        "{%0,%1,%2,%3}, {%4,%5,%6,%7}, {%8,%9}, {%0,%1,%2,%3};"
        : "+f"(c[0]), "+f"(c[1]), "+f"(c[2]), "+f"(c[3])
        : "r"(a[0]), "r"(a[1]), "r"(a[2]), "r"(a[3]), "r"(b[0]), "r"(b[1]));
}

// ============================================================================
// convA: split X fp32 -> bf16 hi/lo (coalesced)
// ============================================================================
__global__ void __launch_bounds__(256) convA_kernel(const float* __restrict__ X) {
    int i = blockIdx.x * 256 + threadIdx.x;             // float4 index
    float4 v = reinterpret_cast<const float4*>(X)[i];
    __nv_bfloat16 h[4], l[4];
    float f[4] = {v.x, v.y, v.z, v.w};
#pragma unroll
    for (int j = 0; j < 4; j++) {
        h[j] = __float2bfloat16(f[j]);
        l[j] = __float2bfloat16(f[j] - __bfloat162float(h[j]));
    }
    *reinterpret_cast<__nv_bfloat162*>(&g_XH[4 * i])     = __nv_bfloat162(h[0], h[1]);
    *reinterpret_cast<__nv_bfloat162*>(&g_XH[4 * i + 2]) = __nv_bfloat162(h[2], h[3]);
    *reinterpret_cast<__nv_bfloat162*>(&g_XL[4 * i])     = __nv_bfloat162(l[0], l[1]);
    *reinterpret_cast<__nv_bfloat162*>(&g_XL[4 * i + 2]) = __nv_bfloat162(l[2], l[3]);
}

// ============================================================================
// convB: W [R][C] -> Bt hi/lo [C][R] (smem tile transpose + split)
// layer 0: W1 [768][512] -> g_BtH/L ; layer 1: W2 [512][128] -> g_Bt2H/L
// ============================================================================
__global__ void __launch_bounds__(256) convB_kernel(const float* __restrict__ W, int layer) {
    const int R = (layer == 0) ? DIN : F1;
    const int C = (layer == 0) ? F1 : CD;
    __nv_bfloat16* dH = (layer == 0) ? g_BtH : g_Bt2H;
    __nv_bfloat16* dL = (layer == 0) ? g_BtL : g_Bt2L;
    __shared__ float t[32][33];
    int tx = threadIdx.x & 31, ty = threadIdx.x >> 5;   // 32x8
    int k0 = blockIdx.x * 32, n0 = blockIdx.y * 32;
#pragma unroll
    for (int j = 0; j < 4; j++)
        t[ty + j * 8][tx] = W[(k0 + ty + j * 8) * C + n0 + tx];
    __syncthreads();
#pragma unroll
    for (int j = 0; j < 4; j++) {
        float v = t[tx][ty + j * 8];
        __nv_bfloat16 h = __float2bfloat16(v);
        __nv_bfloat16 l = __float2bfloat16(v - __bfloat162float(h));
        dH[(size_t)(n0 + ty + j * 8) * R + k0 + tx] = h;
        dL[(size_t)(n0 + ty + j * 8) * R + k0 + tx] = l;
    }
}

// ============================================================================
// GEMM via mma.sync split-bf16 + fused s/t epilogue (both layers).
// grid (M/128, N/128): bm = bx*128, head = by. 256 threads, 8 warps.
// Warp grid 2(m) x 4(n); warp tile 64x32; mma m16n8k16; 3 products per tile.
// smem: [2 stages][4 tiles: AH, AL, BH, BL][128 rows x 40 bf16 (80B stride)].
// ============================================================================
__global__ void __launch_bounds__(256)
gemm_mma_kernel(int layer, const float* __restrict__ asrc, const float* __restrict__ adst) {
    extern __shared__ __align__(16) char sm[];
    const __nv_bfloat16* AH = (layer == 0) ? g_XH  : g_x1H;
    const __nv_bfloat16* AL = (layer == 0) ? g_XL  : g_x1L;
    const __nv_bfloat16* BH = (layer == 0) ? g_BtH : g_Bt2H;
    const __nv_bfloat16* BL = (layer == 0) ? g_BtL : g_Bt2L;
    float* Cout = (layer == 0) ? g_h1 : g_h2;
    float* gs   = (layer == 0) ? g_s1 : g_s2;
    float* gt   = (layer == 0) ? g_t1 : g_t2;
    const int ldk = (layer == 0) ? DIN : F1;
    const int ldc = (layer == 0) ? F1 : CD;
    const int nchunks = (layer == 0) ? NCH1 : (F1 / BK1);

    const int tid = threadIdx.x;
    const int wid = tid >> 5, lane = tid & 31;
    const int gid = lane >> 2, tg = lane & 3;
    const int bm = blockIdx.x * 128, head = blockIdx.y, bn = head * 128;
    const int mw = wid & 1, nw = wid >> 1;
    const int mwb = mw * 64, nwb = nw * 32;

    float acc[4][4][4];
#pragma unroll
    for (int mi = 0; mi < 4; mi++)
#pragma unroll
        for (int ni = 0; ni < 4; ni++)
#pragma unroll
            for (int q = 0; q < 4; q++) acc[mi][ni][q] = 0.f;

    const __nv_bfloat16* srcs[4] = {AH, AL, BH, BL};
    const int rb[4] = {bm, bm, bn, bn};

    float4 pre[8];
    // prefetch chunk 0
#pragma unroll
    for (int t8 = 0; t8 < 8; t8++) {
        int tI = t8 >> 1;
        int i = (t8 & 1) * 256 + tid;
        int row = i >> 2, f4 = i & 3;
        pre[t8] = *reinterpret_cast<const float4*>(
            &srcs[tI][(size_t)(rb[tI] + row) * ldk + f4 * 8]);
    }
    // store chunk 0 into stage 0
#pragma unroll
    for (int t8 = 0; t8 < 8; t8++) {
        int tI = t8 >> 1;
        int i = (t8 & 1) * 256 + tid;
        int row = i >> 2, f4 = i & 3;
        *reinterpret_cast<float4*>(sm + (size_t)tI * TILEB + row * 80 + f4 * 16) = pre[t8];
    }
    __syncthreads();

    for (int ch = 0; ch < nchunks; ch++) {
        const int cur = ch & 1;
        char* tAH = sm + (size_t)(cur * 4 + 0) * TILEB;
        char* tAL = sm + (size_t)(cur * 4 + 1) * TILEB;
        char* tBH = sm + (size_t)(cur * 4 + 2) * TILEB;
        char* tBL = sm + (size_t)(cur * 4 + 3) * TILEB;

        if (ch + 1 < nchunks) {
            const int k0 = (ch + 1) * BK1;
#pragma unroll
            for (int t8 = 0; t8 < 8; t8++) {
                int tI = t8 >> 1;
                int i = (t8 & 1) * 256 + tid;
                int row = i >> 2, f4 = i & 3;
                pre[t8] = *reinterpret_cast<const float4*>(
                    &srcs[tI][(size_t)(rb[tI] + row) * ldk + k0 + f4 * 8]);
            }
        }

#pragma unroll
        for (int ks = 0; ks < 2; ks++) {
            const int kk = ks * 16;
            uint32_t aH[4][4], aL[4][4];
#pragma unroll
            for (int mi = 0; mi < 4; mi++) {
                int r0 = mwb + mi * 16 + gid;
                int co = (kk + tg * 2) * 2;
                aH[mi][0] = *reinterpret_cast<const uint32_t*>(tAH + r0 * 80 + co);
                aH[mi][1] = *reinterpret_cast<const uint32_t*>(tAH + (r0 + 8) * 80 + co);
                aH[mi][2] = *reinterpret_cast<const uint32_t*>(tAH + r0 * 80 + co + 16);
                aH[mi][3] = *reinterpret_cast<const uint32_t*>(tAH + (r0 + 8) * 80 + co + 16);
                aL[mi][0] = *reinterpret_cast<const uint32_t*>(tAL + r0 * 80 + co);
                aL[mi][1] = *reinterpret_cast<const uint32_t*>(tAL + (r0 + 8) * 80 + co);
                aL[mi][2] = *reinterpret_cast<const uint32_t*>(tAL + r0 * 80 + co + 16);
                aL[mi][3] = *reinterpret_cast<const uint32_t*>(tAL + (r0 + 8) * 80 + co + 16);
            }
            uint32_t bH[4][2], bL[4][2];
#pragma unroll
            for (int ni = 0; ni < 4; ni++) {
                int c0 = nwb + ni * 8 + gid;
                int co = (kk + tg * 2) * 2;
                bH[ni][0] = *reinterpret_cast<const uint32_t*>(tBH + c0 * 80 + co);
                bH[ni][1] = *reinterpret_cast<const uint32_t*>(tBH + c0 * 80 + co + 16);
                bL[ni][0] = *reinterpret_cast<const uint32_t*>(tBL + c0 * 80 + co);
                bL[ni][1] = *reinterpret_cast<const uint32_t*>(tBL + c0 * 80 + co + 16);
            }
#pragma unroll
            for (int mi = 0; mi < 4; mi++)
#pragma unroll
                for (int ni = 0; ni < 4; ni++) {
                    mma_bf16(acc[mi][ni], aH[mi], bH[ni]);
                    mma_bf16(acc[mi][ni], aH[mi], bL[ni]);
                    mma_bf16(acc[mi][ni], aL[mi], bH[ni]);
                }
        }

        if (ch + 1 < nchunks) {
            const int nxt = cur ^ 1;
#pragma unroll
            for (int t8 = 0; t8 < 8; t8++) {
                int tI = t8 >> 1;
                int i = (t8 & 1) * 256 + tid;
                int row = i >> 2, f4 = i & 3;
                *reinterpret_cast<float4*>(sm + (size_t)(nxt * 4 + tI) * TILEB +
                                           row * 80 + f4 * 16) = pre[t8];
            }
        }
        __syncthreads();
    }

    // epilogue: store C, per-row s/t partials, cross-warp reduce via smem
    float* sredS = reinterpret_cast<float*>(sm);            // [128][4]
    float* sredT = reinterpret_cast<float*>(sm) + 512;      // [128][4]

#pragma unroll
    for (int mi = 0; mi < 4; mi++) {
        int r0 = mwb + mi * 16 + gid;
        float sp0 = 0.f, sp1 = 0.f, tp0 = 0.f, tp1 = 0.f;
#pragma unroll
        for (int ni = 0; ni < 4; ni++) {
            int col = nwb + ni * 8 + tg * 2;
            float2 av = *reinterpret_cast<const float2*>(&asrc[head * CD + col]);
            float2 dv = *reinterpret_cast<const float2*>(&adst[head * CD + col]);
            *reinterpret_cast<float2*>(&Cout[(size_t)(bm + r0) * ldc + bn + col]) =
                make_float2(acc[mi][ni][0], acc[mi][ni][1]);
            *reinterpret_cast<float2*>(&Cout[(size_t)(bm + r0 + 8) * ldc + bn + col]) =
                make_float2(acc[mi][ni][2], acc[mi][ni][3]);
            sp0 += acc[mi][ni][0] * av.x + acc[mi][ni][1] * av.y;
            tp0 += acc[mi][ni][0] * dv.x + acc[mi][ni][1] * dv.y;
            sp1 += acc[mi][ni][2] * av.x + acc[mi][ni][3] * av.y;
            tp1 += acc[mi][ni][2] * dv.x + acc[mi][ni][3] * dv.y;
        }
#pragma unroll
        for (int o = 1; o < 4; o <<= 1) {
            sp0 += __shfl_xor_sync(0xffffffffu, sp0, o);
            tp0 += __shfl_xor_sync(0xffffffffu, tp0, o);
            sp1 += __shfl_xor_sync(0xffffffffu, sp1, o);
            tp1 += __shfl_xor_sync(0xffffffffu, tp1, o);
        }
        acc[mi][0][0] = sp0; acc[mi][0][1] = tp0;   // stash in acc storage
        acc[mi][0][2] = sp1; acc[mi][0][3] = tp1;
    }
    __syncthreads();   // all tile reads done; safe to reuse smem
#pragma unroll
    for (int mi = 0; mi < 4; mi++) {
        int r0 = mwb + mi * 16 + gid;
        if (tg == 0) {
            sredS[r0 * 4 + nw] = acc[mi][0][0];
            sredT[r0 * 4 + nw] = acc[mi][0][1];
            sredS[(r0 + 8) * 4 + nw] = acc[mi][0][2];
            sredT[(r0 + 8) * 4 + nw] = acc[mi][0][3];
        }
    }
    __syncthreads();
    if (tid < 128) {
        float s = sredS[tid * 4] + sredS[tid * 4 + 1] + sredS[tid * 4 + 2] + sredS[tid * 4 + 3];
        float t = sredT[tid * 4] + sredT[tid * 4 + 1] + sredT[tid * 4 + 2] + sredT[tid * 4 + 3];
        gs[head * NN + bm + tid] = s;
        gt[head * NN + bm + tid] = t;
    }
}

// ============================================================================
// Sort stage 1: bitonic sort of 512-element chunks.
// 128 threads x 4 elems. j<=2 in regs, 4<=j<=64 via shfl_xor,
// j>=128 via smem (only 3 stages: k=256 j=128; k=512 j=256,128).
// ============================================================================
__device__ __forceinline__ void cswap(ull& a, ull& b, bool asc) {
    if ((a > b) == asc) { ull t = a; a = b; b = t; }
}

__global__ void __launch_bounds__(128)
sortchunk_kernel(int layer) {
    const float* s = (layer == 0) ? g_s1 : g_s2;
    const int head = blockIdx.y, chunk = blockIdx.x;
    const int tid = threadIdx.x;
    const int i0 = 4 * tid;
    __shared__ ull kv[SC];

    ull v[4];
    const int gbase = head * NN + chunk * SC;
#pragma unroll
    for (int e = 0; e < 4; e++) {
        unsigned u = __float_as_uint(s[gbase + i0 + e]);
        u = (u & 0x80000000u) ? ~u : (u | 0x80000000u);
        v[e] = ((ull)u << 32) | (unsigned)(chunk * SC + i0 + e);
    }

    // k=2, k=4 in registers
    cswap(v[0], v[1], true); cswap(v[2], v[3], false);
    {
        bool asc = ((i0 & 4) == 0);
        cswap(v[0], v[2], asc); cswap(v[1], v[3], asc);
        cswap(v[0], v[1], asc); cswap(v[2], v[3], asc);
    }

    // k = 8..128: all stages via shfl + regs (no smem, no syncs)
#pragma unroll
    for (int k = 8; k <= 128; k <<= 1) {
        const bool asc = ((i0 & k) == 0);
#pragma unroll
        for (int j = k >> 1; j >= 4; j >>= 1) {
            const bool keepmin = (((i0 & j) == 0) == asc);
#pragma unroll
            for (int e = 0; e < 4; e++) {
                ull o = __shfl_xor_sync(0xffffffffu, v[e], j >> 2);
                ull mn = (v[e] < o) ? v[e] : o;
                ull mx = (v[e] < o) ? o : v[e];
                v[e] = keepmin ? mn : mx;
            }
        }
        cswap(v[0], v[2], asc); cswap(v[1], v[3], asc);
        cswap(v[0], v[1], asc); cswap(v[2], v[3], asc);
    }

    // k = 256, 512: j>=128 via smem, then shfl/regs
    for (int k = 256; k <= SC; k <<= 1) {
#pragma unroll
        for (int e = 0; e < 4; e++) kv[i0 + e] = v[e];
        __syncthreads();
        for (int j = k >> 1; j >= 128; j >>= 1) {
#pragma unroll
            for (int e = 0; e < 4; e++) {
                int i = tid + e * 128;
                if ((i & j) == 0) {
                    int p = i | j;
                    ull a = kv[i], b = kv[p];
                    bool asc2 = ((i & k) == 0);
                    if ((a > b) == asc2) { kv[i] = b; kv[p] = a; }
                }
            }
            __syncthreads();
        }
#pragma unroll
        for (int e = 0; e < 4; e++) v[e] = kv[i0 + e];
        const bool asc = ((i0 & k) == 0);
#pragma unroll
        for (int j = 64; j >= 4; j >>= 1) {
            const bool keepmin = (((i0 & j) == 0) == asc);
#pragma unroll
            for (int e = 0; e < 4; e++) {
                ull o = __shfl_xor_sync(0xffffffffu, v[e], j >> 2);
                ull mn = (v[e] < o) ? v[e] : o;
                ull mx = (v[e] < o) ? o : v[e];
                v[e] = keepmin ? mn : mx;
            }
        }
        cswap(v[0], v[2], asc); cswap(v[1], v[3], asc);
        cswap(v[0], v[1], asc); cswap(v[2], v[3], asc);
        __syncthreads();   // protect kv before next k's store
    }

#pragma unroll
    for (int e = 0; e < 4; e++)
        g_sc[gbase + i0 + e] = v[e];
}

// ============================================================================
// Sort stage 2: rank-merge of 8 sorted chunks (7 interleaved gallops, exact)
// + fused weights w0=exp(0.2 s), w1=exp(s).
// ============================================================================
__global__ void __launch_bounds__(256)
merge_kernel(int layer, int H) {
    float* ss = (layer == 0) ? g_ss1 : g_ss2;
    int*   si = (layer == 0) ? g_si1 : g_si2;
    float* w0 = (layer == 0) ? g_w0_1 : g_w0_2;
    float* w1 = (layer == 0) ? g_w1_1 : g_w1_2;

    int gid = blockIdx.x * 256 + threadIdx.x;
    if (gid >= H * NN) return;
    int head = gid >> 12;
    int i = gid & (NN - 1);
    int c = i / SC, p = i & (SC - 1);

    const ull* base = g_sc + (size_t)head * NN;
    ull v = base[c * SC + p];

    const ull* oth[NSC - 1];
    int cc = 0;
#pragma unroll
    for (int q = 0; q < NSC; q++) if (q != c) oth[cc++] = base + q * SC;

    int pos[NSC - 1];
#pragma unroll
    for (int q = 0; q < NSC - 1; q++) pos[q] = 0;
#pragma unroll
    for (int step = SC; step >= 1; step >>= 1) {
#pragma unroll
        for (int q = 0; q < NSC - 1; q++) {
            bool g = (pos[q] + step <= SC) && (__ldg(&oth[q][pos[q] + step - 1]) < v);
            if (g) pos[q] += step;
        }
    }
    int rank = p;
#pragma unroll
    for (int q = 0; q < NSC - 1; q++) rank += pos[q];

    unsigned ku = (unsigned)(v >> 32);
    float f = (ku & 0x80000000u) ? __uint_as_float(ku ^ 0x80000000u)
                                 : __uint_as_float(~ku);
    ss[head * NN + rank] = f;
    si[head * NN + rank] = (int)(v & 0xffffffffu);
    w0[head * NN + rank] = expf(0.2f * f);
    w1[head * NN + rank] = expf(f);
}

// ============================================================================
// zscan: inclusive prefix (w0) / suffix (w1) scans, shfl-based
// ============================================================================
__global__ void __launch_bounds__(1024)
zscan_kernel(int layer) {
    const int dir = blockIdx.x, head = blockIdx.y;
    const float* w = (layer == 0) ? (dir == 0 ? g_w0_1 : g_w1_1)
                                  : (dir == 0 ? g_w0_2 : g_w1_2);
    float* z = (layer == 0) ? (dir == 0 ? g_z0_1 : g_z1_1)
                            : (dir == 0 ? g_z0_2 : g_z1_2);

    const int tid = threadIdx.x;
    const int lane = tid & 31, warp = tid >> 5;
    __shared__ float wsum[32], woff[32];

    const int i0 = 4 * tid;
    float4 v = *reinterpret_cast<const float4*>(&w[head * NN + i0]);

    if (dir == 0) {
        float p0 = v.x, p1 = p0 + v.y, p2 = p1 + v.z, p3 = p2 + v.w;
        float x = p3;
#pragma unroll
        for (int o = 1; o < 32; o <<= 1) {
            float y = __shfl_up_sync(0xffffffffu, x, o);
            if (lane >= o) x += y;
        }
        float wexcl = x - p3;
        if (lane == 31) wsum[warp] = x;
        __syncthreads();
        if (warp == 0) {
            float t = wsum[lane];
#pragma unroll
            for (int o = 1; o < 32; o <<= 1) {
                float y = __shfl_up_sync(0xffffffffu, t, o);
                if (lane >= o) t += y;
            }
            woff[lane] = t - wsum[lane];
        }
        __syncthreads();
        float off = woff[warp] + wexcl;
        *reinterpret_cast<float4*>(&z[head * NN + i0]) =
            make_float4(p0 + off, p1 + off, p2 + off, p3 + off);
    } else {
        float q3 = v.w, q2 = q3 + v.z, q1 = q2 + v.y, q0 = q1 + v.x;
        float x = q0;
#pragma unroll
        for (int o = 1; o < 32; o <<= 1) {
            float y = __shfl_down_sync(0xffffffffu, x, o);
            if (lane + o < 32) x += y;
        }
        float wexcl = x - q0;
        if (lane == 0) wsum[warp] = x;
        __syncthreads();
        if (warp == 0) {
            float t = wsum[lane];
#pragma unroll
            for (int o = 1; o < 32; o <<= 1) {
                float y = __shfl_down_sync(0xffffffffu, t, o);
                if (lane + o < 32) t += y;
            }
            woff[lane] = t - wsum[lane];
        }
        __syncthreads();
        float off = woff[warp] + wexcl;
        *reinterpret_cast<float4*>(&z[head * NN + i0]) =
            make_float4(q0 + off, q1 + off, q2 + off, q3 + off);
    }
}

// ============================================================================
// ksearch: split points + per-(head,node) scalar coefficients
// ============================================================================
__global__ void __launch_bounds__(256)
ksearch_kernel(int layer, int H) {
    const float* t  = (layer == 0) ? g_t1 : g_t2;
    const float* ss = (layer == 0) ? g_ss1 : g_ss2;
    const float* z0 = (layer == 0) ? g_z0_1 : g_z0_2;
    const float* z1 = (layer == 0) ? g_z1_1 : g_z1_2;
    int*    kk = (layer == 0) ? g_k1 : g_k2;
    float2* aa = (layer == 0) ? g_a1 : g_a2;

    int gid = blockIdx.x * 256 + threadIdx.x;
    if (gid >= H * NN) return;
    int head = gid >> 12;
    const float* ssh = ss + head * NN;
    float tv = t[gid];
    float tau = -tv;
    int pos = 0;
#pragma unroll
    for (int step = NN; step >= 1; step >>= 1) {
        if (pos + step <= NN && __ldg(&ssh[pos + step - 1]) <= tau) pos += step;
    }
    kk[gid] = pos;

    float z0v = (pos > 0)  ? z0[head * NN + pos - 1] : 0.f;
    float z1v = (pos < NN) ? z1[head * NN + pos]     : 0.f;
    float et  = expf(tv);
    float et2 = expf(0.2f * tv);
    float inv = 1.f / (et * z1v + et2 * z0v);
    float a0 = (pos > 0)  ? et2 * inv : 0.f;
    float a1 = (pos < NN) ? et  * inv : 0.f;
    aa[gid] = make_float2(a0, a1);
}

// ============================================================================
// passA: chunked vector scans (MLP=16 gathers)
// ============================================================================
__global__ void __launch_bounds__(CD)
passA_kernel(int layer, int F) {
    const float* h  = (layer == 0) ? g_h1 : g_h2;
    const int*   si = (layer == 0) ? g_si1 : g_si2;
    const float* w0 = (layer == 0) ? g_w0_1 : g_w0_2;
    const float* w1 = (layer == 0) ? g_w1_1 : g_w1_2;
    float* I0 = (layer == 0) ? g_I0_1 : g_I0_2;
    float* S1 = (layer == 0) ? g_S1_1 : g_S1_2;

    const int chunk = blockIdx.x, head = blockIdx.y, dir = blockIdx.z;
    const int c = threadIdx.x;
    const int base = head * NN + chunk * CHUNK;

    __shared__ int   sj[CHUNK];
    __shared__ float sw[CHUNK];
    const float* wsel = (dir == 0) ? w0 : w1;
    for (int r = threadIdx.x; r < CHUNK; r += blockDim.x) {
        sj[r] = si[base + r] * F + head * CD;
        sw[r] = wsel[base + r];
    }
    __syncthreads();

    float acc = 0.f;
    if (dir == 0) {
        float* dst = I0 + (size_t)base * CD + c;
        for (int rr = 0; rr < CHUNK; rr += 16) {
            float v[16];
#pragma unroll
            for (int u = 0; u < 16; u++) v[u] = __ldg(&h[sj[rr + u] + c]);
#pragma unroll
            for (int u = 0; u < 16; u++) {
                acc = fmaf(sw[rr + u], v[u], acc);
                dst[(size_t)(rr + u) * CD] = acc;
            }
        }
    } else {
        float* dst = S1 + (size_t)base * CD + c;
        for (int rr = CHUNK - 16; rr >= 0; rr -= 16) {
            float v[16];
#pragma unroll
            for (int u = 15; u >= 0; u--) v[u] = __ldg(&h[sj[rr + u] + c]);
#pragma unroll
            for (int u = 15; u >= 0; u--) {
                acc = fmaf(sw[rr + u], v[u], acc);
                dst[(size_t)(rr + u) * CD] = acc;
            }
        }
    }
}

// ---------------- cross-chunk offsets ----------------
__global__ void passB_kernel(int layer) {
    const float* I0 = (layer == 0) ? g_I0_1 : g_I0_2;
    const float* S1 = (layer == 0) ? g_S1_1 : g_S1_2;
    float* O0 = (layer == 0) ? g_O0_1 : g_O0_2;
    float* O1 = (layer == 0) ? g_O1_1 : g_O1_2;

    int head = blockIdx.x, c = threadIdx.x;
    float acc = 0.f;
    for (int ch = 0; ch < NCH; ch++) {
        O0[(head * NCH + ch) * CD + c] = acc;
        acc += I0[(head * NN + ch * CHUNK + CHUNK - 1) * CD + c];
    }
    acc = 0.f;
    for (int ch = NCH - 1; ch >= 0; ch--) {
        O1[(head * NCH + ch) * CD + c] = acc;
        acc += S1[(head * NN + ch * CHUNK) * CD + c];
    }
}

// ---------------- lookup: 2 clamped table reads + 2 FMA + elu ----------------
// Layer 0 writes x1 directly as split bf16 (feeds mma GEMM2); layer 1 writes fp32.
__global__ void __launch_bounds__(CD)
lookup_kernel(int layer, const float* __restrict__ bias, int F) {
    const int*    kk = (layer == 0) ? g_k1 : g_k2;
    const float2* aa = (layer == 0) ? g_a1 : g_a2;
    const float* I0 = (layer == 0) ? g_I0_1 : g_I0_2;
    const float* S1 = (layer == 0) ? g_S1_1 : g_S1_2;
    const float* O0 = (layer == 0) ? g_O0_1 : g_O0_2;
    const float* O1 = (layer == 0) ? g_O1_1 : g_O1_2;

    int head = blockIdx.y, c = threadIdx.x;
    float bv = bias[head * CD + c];

#pragma unroll 2
    for (int u = 0; u < 8; u++) {
        int i = blockIdx.x * 8 + u;
        int k = kk[head * NN + i];
        float2 a = aa[head * NN + i];

        int k0i = (k > 0) ? (k - 1) : 0;
        int k1i = (k < NN) ? k : (NN - 1);
        float A0 = I0[(size_t)(head * NN + k0i) * CD + c] +
                   O0[(head * NCH + k0i / CHUNK) * CD + c];
        float A1 = S1[(size_t)(head * NN + k1i) * CD + c] +
                   O1[(head * NCH + k1i / CHUNK) * CD + c];
        float o = fmaf(a.y, A1, fmaf(a.x, A0, bv));
        float x = elu1(o);
        size_t idx = (size_t)i * F + head * CD + c;
        if (layer == 0) {
            __nv_bfloat16 hh = __float2bfloat16(x);
            g_x1H[idx] = hh;
            g_x1L[idx] = __float2bfloat16(x - __bfloat162float(hh));
        } else {
            g_x2[idx] = x;
        }
    }
}

// ---------------- column mean + FC ----------------
__global__ void colpart_kernel() {
    int b = blockIdx.x, c = threadIdx.x;
    float acc = 0.f;
    for (int r = 0; r < NN / 32; r++) acc += g_x2[(b * (NN / 32) + r) * CD + c];
    g_part[b * CD + c] = acc;
}
__global__ void __launch_bounds__(DIN)
colfinal_fc_kernel(const float* __restrict__ fcW, const float* __restrict__ fcb,
                   float* __restrict__ out) {
    __shared__ float m[CD];
    int tid = threadIdx.x;
    if (tid < CD) {
        float a = 0.f;
        for (int b = 0; b < 32; b++) a += g_part[b * CD + tid];
        m[tid] = a * (1.f / (float)NN);
    }
    __syncthreads();
    if (tid < DIN) {
        float acc = fcb[tid];
#pragma unroll 8
        for (int c = 0; c < CD; c++) acc = fmaf(m[c], fcW[c * DIN + tid], acc);
        out[tid] = acc;
    }
}

// ---------------- launch ----------------
extern "C" void kernel_launch(void* const* d_in, const int* in_sizes, int n_in,
                              void* d_out, int out_size) {
    const float* X   = (const float*)d_in[0];
    const float* W1  = (const float*)d_in[1];
    const float* as1 = (const float*)d_in[2];
    const float* ad1 = (const float*)d_in[3];
    const float* b1  = (const float*)d_in[4];
    const float* W2  = (const float*)d_in[5];
    const float* as2 = (const float*)d_in[6];
    const float* ad2 = (const float*)d_in[7];
    const float* b2  = (const float*)d_in[8];
    const float* fcW = (const float*)d_in[9];
    const float* fcb = (const float*)d_in[10];
    float* out = (float*)d_out;

    const int MMA_SMEM = 2 * 4 * TILEB;   // 81920 bytes
    cudaFuncSetAttribute(gemm_mma_kernel,
                         cudaFuncAttributeMaxDynamicSharedMemorySize, MMA_SMEM);

    // conv kernels first (convB layer1 hoisted: no dependency; makes launch #4
    // the layer-0 GEMM so ncu's capture lands on it)
    convA_kernel<<<(NN * DIN / 4) / 256, 256>>>(X);
    convB_kernel<<<dim3(DIN / 32, F1 / 32), 256>>>(W1, 0);
    convB_kernel<<<dim3(F1 / 32, CD / 32), 256>>>(W2, 1);

    // Layer 1: split-bf16 mma.sync GEMM (M=4096, K=768, N=512)
    gemm_mma_kernel<<<dim3(NN / 128, HH1), 256, MMA_SMEM>>>(0, as1, ad1);
    sortchunk_kernel<<<dim3(NSC, HH1), 128>>>(0);
    merge_kernel<<<(HH1 * NN) / 256, 256>>>(0, HH1);
    zscan_kernel<<<dim3(2, HH1), 1024>>>(0);
    ksearch_kernel<<<(HH1 * NN) / 256, 256>>>(0, HH1);
    passA_kernel<<<dim3(NCH, HH1, 2), CD>>>(0, F1);
    passB_kernel<<<HH1, CD>>>(0);
    lookup_kernel<<<dim3(NN / 8, HH1), CD>>>(0, b1, F1);

    // Layer 2: split-bf16 mma.sync GEMM (M=4096, K=512, N=128)
    gemm_mma_kernel<<<dim3(NN / 128, 1), 256, MMA_SMEM>>>(1, as2, ad2);
    sortchunk_kernel<<<dim3(NSC, 1), 128>>>(1);
    merge_kernel<<<NN / 256, 256>>>(1, 1);
    zscan_kernel<<<dim3(2, 1), 1024>>>(1);
    ksearch_kernel<<<NN / 256, 256>>>(1, 1);
    passA_kernel<<<dim3(NCH, 1, 2), CD>>>(1, CD);
    passB_kernel<<<1, CD>>>(1);
    lookup_kernel<<<dim3(NN / 8, 1), CD>>>(1, b2, CD);

    // Mean + FC
    colpart_kernel<<<32, CD>>>();
    colfinal_fc_kernel<<<1, DIN>>>(fcW, fcb, out);
}

// round 17
// speedup vs baseline: 1.4152x; 1.4152x over previous
#include <cuda_runtime.h>
#include <cuda_bf16.h>
#include <stdint.h>
#include <math.h>

#define NN    4096
#define DIN   768
#define CD    128
#define HH1   4
#define F1    512
#define CHUNK 256
#define NCH   (NN/CHUNK)   // 16 (passA chunks)
#define SC    1024         // sort chunk size (R13 config)
#define NSC   4            // sort chunks
#define BK1   32           // mma gemm K-chunk
#define NCH1  (DIN/BK1)    // 24 (layer1); layer2 uses F1/BK1 = 16
#define TSTR  40           // smem row stride in bf16 elems (80B) -> conflict-free frags
#define TILEB (128*TSTR*2) // 10240 B per tile

typedef unsigned long long ull;

// ---------------- device scratch (no allocs allowed) ----------------
__device__ float g_h1[NN*F1];
__device__ float g_h2[NN*CD];
__device__ float g_x2[NN*CD];

__device__ __nv_bfloat16 g_XH[NN*DIN],  g_XL[NN*DIN];     // split X
__device__ __nv_bfloat16 g_BtH[F1*DIN], g_BtL[F1*DIN];    // split W1^T [512][768]
__device__ __nv_bfloat16 g_x1H[NN*F1],  g_x1L[NN*F1];     // split x1 (layer2 A)
__device__ __nv_bfloat16 g_Bt2H[CD*F1], g_Bt2L[CD*F1];    // split W2^T [128][512]

__device__ float g_s1[HH1*NN], g_t1[HH1*NN], g_ss1[HH1*NN];
__device__ float g_w0_1[HH1*NN], g_w1_1[HH1*NN], g_z0_1[HH1*NN], g_z1_1[HH1*NN];
__device__ int   g_si1[HH1*NN];
__device__ int   g_k1[HH1*NN];
__device__ float2 g_a1[HH1*NN];
__device__ float g_I0_1[HH1*NN*CD], g_S1_1[HH1*NN*CD];
__device__ float g_O0_1[HH1*NCH*CD], g_O1_1[HH1*NCH*CD];

__device__ float g_s2[NN], g_t2[NN], g_ss2[NN];
__device__ float g_w0_2[NN], g_w1_2[NN], g_z0_2[NN], g_z1_2[NN];
__device__ int   g_si2[NN];
__device__ int   g_k2[NN];
__device__ float2 g_a2[NN];
__device__ float g_I0_2[NN*CD], g_S1_2[NN*CD];
__device__ float g_O0_2[NCH*CD], g_O1_2[NCH*CD];

__device__ ull   g_sc[HH1*NN];

__device__ float g_part[32*CD];

// ---------------- helpers ----------------
__device__ __forceinline__ float elu1(float x) { return x > 0.f ? x : expm1f(x); }

// mma.sync bf16 (sm_80+ ISA; compiles on compute_103 base target)
__device__ __forceinline__ void mma_bf16(float* c, const uint32_t* a, const uint32_t* b) {
    asm volatile(
        "mma.sync.aligned.m16n8k16.row.col.f32.bf16.bf16.f32 "
        "{%0,%1,%2,%3}, {%4,%5,%6,%7}, {%8,%9}, {%0,%1,%2,%3};"
        : "+f"(c[0]), "+f"(c[1]), "+f"(c[2]), "+f"(c[3])
        : "r"(a[0]), "r"(a[1]), "r"(a[2]), "r"(a[3]), "r"(b[0]), "r"(b[1]));
}

// ============================================================================
// convA: split X fp32 -> bf16 hi/lo (coalesced)
// ============================================================================
__global__ void __launch_bounds__(256) convA_kernel(const float* __restrict__ X) {
    int i = blockIdx.x * 256 + threadIdx.x;             // float4 index
    float4 v = reinterpret_cast<const float4*>(X)[i];
    __nv_bfloat16 h[4], l[4];
    float f[4] = {v.x, v.y, v.z, v.w};
#pragma unroll
    for (int j = 0; j < 4; j++) {
        h[j] = __float2bfloat16(f[j]);
        l[j] = __float2bfloat16(f[j] - __bfloat162float(h[j]));
    }
    *reinterpret_cast<__nv_bfloat162*>(&g_XH[4 * i])     = __nv_bfloat162(h[0], h[1]);
    *reinterpret_cast<__nv_bfloat162*>(&g_XH[4 * i + 2]) = __nv_bfloat162(h[2], h[3]);
    *reinterpret_cast<__nv_bfloat162*>(&g_XL[4 * i])     = __nv_bfloat162(l[0], l[1]);
    *reinterpret_cast<__nv_bfloat162*>(&g_XL[4 * i + 2]) = __nv_bfloat162(l[2], l[3]);
}

// ============================================================================
// convB: W [R][C] -> Bt hi/lo [C][R] (smem tile transpose + split)
// ============================================================================
__global__ void __launch_bounds__(256) convB_kernel(const float* __restrict__ W, int layer) {
    const int R = (layer == 0) ? DIN : F1;
    const int C = (layer == 0) ? F1 : CD;
    __nv_bfloat16* dH = (layer == 0) ? g_BtH : g_Bt2H;
    __nv_bfloat16* dL = (layer == 0) ? g_BtL : g_Bt2L;
    __shared__ float t[32][33];
    int tx = threadIdx.x & 31, ty = threadIdx.x >> 5;   // 32x8
    int k0 = blockIdx.x * 32, n0 = blockIdx.y * 32;
#pragma unroll
    for (int j = 0; j < 4; j++)
        t[ty + j * 8][tx] = W[(k0 + ty + j * 8) * C + n0 + tx];
    __syncthreads();
#pragma unroll
    for (int j = 0; j < 4; j++) {
        float v = t[tx][ty + j * 8];
        __nv_bfloat16 h = __float2bfloat16(v);
        __nv_bfloat16 l = __float2bfloat16(v - __bfloat162float(h));
        dH[(size_t)(n0 + ty + j * 8) * R + k0 + tx] = h;
        dL[(size_t)(n0 + ty + j * 8) * R + k0 + tx] = l;
    }
}

// ============================================================================
// GEMM via mma.sync split-bf16 + fused s/t epilogue (both layers).
// grid (M/128, N/128). 512 threads, 16 warps (4/SMSP for latency hiding).
// Warp grid 4(m) x 4(n); warp tile 32x32; mma m16n8k16; 3 products per tile.
// smem: [2 stages][4 tiles: AH, AL, BH, BL][128 rows x 40 bf16 (80B stride)].
// ============================================================================
__global__ void __launch_bounds__(512)
gemm_mma_kernel(int layer, const float* __restrict__ asrc, const float* __restrict__ adst) {
    extern __shared__ __align__(16) char sm[];
    const __nv_bfloat16* AH = (layer == 0) ? g_XH  : g_x1H;
    const __nv_bfloat16* AL = (layer == 0) ? g_XL  : g_x1L;
    const __nv_bfloat16* BH = (layer == 0) ? g_BtH : g_Bt2H;
    const __nv_bfloat16* BL = (layer == 0) ? g_BtL : g_Bt2L;
    float* Cout = (layer == 0) ? g_h1 : g_h2;
    float* gs   = (layer == 0) ? g_s1 : g_s2;
    float* gt   = (layer == 0) ? g_t1 : g_t2;
    const int ldk = (layer == 0) ? DIN : F1;
    const int ldc = (layer == 0) ? F1 : CD;
    const int nchunks = (layer == 0) ? NCH1 : (F1 / BK1);

    const int tid = threadIdx.x;
    const int wid = tid >> 5, lane = tid & 31;
    const int gid = lane >> 2, tg = lane & 3;
    const int bm = blockIdx.x * 128, head = blockIdx.y, bn = head * 128;
    const int mw = wid & 3, nw = wid >> 2;
    const int mwb = mw * 32, nwb = nw * 32;

    float acc[2][4][4];
#pragma unroll
    for (int mi = 0; mi < 2; mi++)
#pragma unroll
        for (int ni = 0; ni < 4; ni++)
#pragma unroll
            for (int q = 0; q < 4; q++) acc[mi][ni][q] = 0.f;

    const __nv_bfloat16* srcs[4] = {AH, AL, BH, BL};
    const int rb[4] = {bm, bm, bn, bn};

    float4 pre[4];
    // prefetch chunk 0 (2048 float4 slots / 512 threads = 4 each)
#pragma unroll
    for (int t4 = 0; t4 < 4; t4++) {
        int idx = t4 * 512 + tid;
        int tI = idx >> 9, i = idx & 511;
        int row = i >> 2, f4 = i & 3;
        pre[t4] = *reinterpret_cast<const float4*>(
            &srcs[tI][(size_t)(rb[tI] + row) * ldk + f4 * 8]);
    }
    // store chunk 0 into stage 0
#pragma unroll
    for (int t4 = 0; t4 < 4; t4++) {
        int idx = t4 * 512 + tid;
        int tI = idx >> 9, i = idx & 511;
        int row = i >> 2, f4 = i & 3;
        *reinterpret_cast<float4*>(sm + (size_t)tI * TILEB + row * 80 + f4 * 16) = pre[t4];
    }
    __syncthreads();

    for (int ch = 0; ch < nchunks; ch++) {
        const int cur = ch & 1;
        char* tAH = sm + (size_t)(cur * 4 + 0) * TILEB;
        char* tAL = sm + (size_t)(cur * 4 + 1) * TILEB;
        char* tBH = sm + (size_t)(cur * 4 + 2) * TILEB;
        char* tBL = sm + (size_t)(cur * 4 + 3) * TILEB;

        if (ch + 1 < nchunks) {
            const int k0 = (ch + 1) * BK1;
#pragma unroll
            for (int t4 = 0; t4 < 4; t4++) {
                int idx = t4 * 512 + tid;
                int tI = idx >> 9, i = idx & 511;
                int row = i >> 2, f4 = i & 3;
                pre[t4] = *reinterpret_cast<const float4*>(
                    &srcs[tI][(size_t)(rb[tI] + row) * ldk + k0 + f4 * 8]);
            }
        }

#pragma unroll
        for (int ks = 0; ks < 2; ks++) {
            const int kk = ks * 16;
            uint32_t aH[2][4], aL[2][4];
#pragma unroll
            for (int mi = 0; mi < 2; mi++) {
                int r0 = mwb + mi * 16 + gid;
                int co = (kk + tg * 2) * 2;
                aH[mi][0] = *reinterpret_cast<const uint32_t*>(tAH + r0 * 80 + co);
                aH[mi][1] = *reinterpret_cast<const uint32_t*>(tAH + (r0 + 8) * 80 + co);
                aH[mi][2] = *reinterpret_cast<const uint32_t*>(tAH + r0 * 80 + co + 16);
                aH[mi][3] = *reinterpret_cast<const uint32_t*>(tAH + (r0 + 8) * 80 + co + 16);
                aL[mi][0] = *reinterpret_cast<const uint32_t*>(tAL + r0 * 80 + co);
                aL[mi][1] = *reinterpret_cast<const uint32_t*>(tAL + (r0 + 8) * 80 + co);
                aL[mi][2] = *reinterpret_cast<const uint32_t*>(tAL + r0 * 80 + co + 16);
                aL[mi][3] = *reinterpret_cast<const uint32_t*>(tAL + (r0 + 8) * 80 + co + 16);
            }
            uint32_t bH[4][2], bL[4][2];
#pragma unroll
            for (int ni = 0; ni < 4; ni++) {
                int c0 = nwb + ni * 8 + gid;
                int co = (kk + tg * 2) * 2;
                bH[ni][0] = *reinterpret_cast<const uint32_t*>(tBH + c0 * 80 + co);
                bH[ni][1] = *reinterpret_cast<const uint32_t*>(tBH + c0 * 80 + co + 16);
                bL[ni][0] = *reinterpret_cast<const uint32_t*>(tBL + c0 * 80 + co);
                bL[ni][1] = *reinterpret_cast<const uint32_t*>(tBL + c0 * 80 + co + 16);
            }
#pragma unroll
            for (int mi = 0; mi < 2; mi++)
#pragma unroll
                for (int ni = 0; ni < 4; ni++) {
                    mma_bf16(acc[mi][ni], aH[mi], bH[ni]);
                    mma_bf16(acc[mi][ni], aH[mi], bL[ni]);
                    mma_bf16(acc[mi][ni], aL[mi], bH[ni]);
                }
        }

        if (ch + 1 < nchunks) {
            const int nxt = cur ^ 1;
#pragma unroll
            for (int t4 = 0; t4 < 4; t4++) {
                int idx = t4 * 512 + tid;
                int tI = idx >> 9, i = idx & 511;
                int row = i >> 2, f4 = i & 3;
                *reinterpret_cast<float4*>(sm + (size_t)(nxt * 4 + tI) * TILEB +
                                           row * 80 + f4 * 16) = pre[t4];
            }
        }
        __syncthreads();
    }

    // epilogue: store C, per-row s/t partials, cross-warp reduce via smem
    float* sredS = reinterpret_cast<float*>(sm);            // [128][4]
    float* sredT = reinterpret_cast<float*>(sm) + 512;      // [128][4]

#pragma unroll
    for (int mi = 0; mi < 2; mi++) {
        int r0 = mwb + mi * 16 + gid;
        float sp0 = 0.f, sp1 = 0.f, tp0 = 0.f, tp1 = 0.f;
#pragma unroll
        for (int ni = 0; ni < 4; ni++) {
            int col = nwb + ni * 8 + tg * 2;
            float2 av = *reinterpret_cast<const float2*>(&asrc[head * CD + col]);
            float2 dv = *reinterpret_cast<const float2*>(&adst[head * CD + col]);
            *reinterpret_cast<float2*>(&Cout[(size_t)(bm + r0) * ldc + bn + col]) =
                make_float2(acc[mi][ni][0], acc[mi][ni][1]);
            *reinterpret_cast<float2*>(&Cout[(size_t)(bm + r0 + 8) * ldc + bn + col]) =
                make_float2(acc[mi][ni][2], acc[mi][ni][3]);
            sp0 += acc[mi][ni][0] * av.x + acc[mi][ni][1] * av.y;
            tp0 += acc[mi][ni][0] * dv.x + acc[mi][ni][1] * dv.y;
            sp1 += acc[mi][ni][2] * av.x + acc[mi][ni][3] * av.y;
            tp1 += acc[mi][ni][2] * dv.x + acc[mi][ni][3] * dv.y;
        }
#pragma unroll
        for (int o = 1; o < 4; o <<= 1) {
            sp0 += __shfl_xor_sync(0xffffffffu, sp0, o);
            tp0 += __shfl_xor_sync(0xffffffffu, tp0, o);
            sp1 += __shfl_xor_sync(0xffffffffu, sp1, o);
            tp1 += __shfl_xor_sync(0xffffffffu, tp1, o);
        }
        acc[mi][0][0] = sp0; acc[mi][0][1] = tp0;   // stash in acc storage
        acc[mi][0][2] = sp1; acc[mi][0][3] = tp1;
    }
    __syncthreads();   // all tile reads done; safe to reuse smem
#pragma unroll
    for (int mi = 0; mi < 2; mi++) {
        int r0 = mwb + mi * 16 + gid;
        if (tg == 0) {
            sredS[r0 * 4 + nw] = acc[mi][0][0];
            sredT[r0 * 4 + nw] = acc[mi][0][1];
            sredS[(r0 + 8) * 4 + nw] = acc[mi][0][2];
            sredT[(r0 + 8) * 4 + nw] = acc[mi][0][3];
        }
    }
    __syncthreads();
    if (tid < 128) {
        float s = sredS[tid * 4] + sredS[tid * 4 + 1] + sredS[tid * 4 + 2] + sredS[tid * 4 + 3];
        float t = sredT[tid * 4] + sredT[tid * 4 + 1] + sredT[tid * 4 + 2] + sredT[tid * 4 + 3];
        gs[head * NN + bm + tid] = s;
        gt[head * NN + bm + tid] = t;
    }
}

// ============================================================================
// Sort stage 1 (R13 config): bitonic sort of 1024-element chunks, 256 threads.
// j<=2 in regs, 4<=j<=64 via shfl_xor, j>=128 via smem.
// ============================================================================
__device__ __forceinline__ void cswap(ull& a, ull& b, bool asc) {
    if ((a > b) == asc) { ull t = a; a = b; b = t; }
}

__global__ void __launch_bounds__(256)
sortchunk_kernel(int layer) {
    const float* s = (layer == 0) ? g_s1 : g_s2;
    const int head = blockIdx.y, chunk = blockIdx.x;
    const int tid = threadIdx.x;
    const int i0 = 4 * tid;
    __shared__ ull kv[SC];

    ull v[4];
    const int gbase = head * NN + chunk * SC;
#pragma unroll
    for (int e = 0; e < 4; e++) {
        unsigned u = __float_as_uint(s[gbase + i0 + e]);
        u = (u & 0x80000000u) ? ~u : (u | 0x80000000u);
        v[e] = ((ull)u << 32) | (unsigned)(chunk * SC + i0 + e);
    }

    cswap(v[0], v[1], true); cswap(v[2], v[3], false);
    {
        bool asc = ((i0 & 4) == 0);
        cswap(v[0], v[2], asc); cswap(v[1], v[3], asc);
        cswap(v[0], v[1], asc); cswap(v[2], v[3], asc);
    }

#pragma unroll
    for (int k = 8; k <= 128; k <<= 1) {
        const bool asc = ((i0 & k) == 0);
#pragma unroll
        for (int j = k >> 1; j >= 4; j >>= 1) {
            const bool keepmin = (((i0 & j) == 0) == asc);
#pragma unroll
            for (int e = 0; e < 4; e++) {
                ull o = __shfl_xor_sync(0xffffffffu, v[e], j >> 2);
                ull mn = (v[e] < o) ? v[e] : o;
                ull mx = (v[e] < o) ? o : v[e];
                v[e] = keepmin ? mn : mx;
            }
        }
        cswap(v[0], v[2], asc); cswap(v[1], v[3], asc);
        cswap(v[0], v[1], asc); cswap(v[2], v[3], asc);
    }

    for (int k = 256; k <= SC; k <<= 1) {
#pragma unroll
        for (int e = 0; e < 4; e++) kv[i0 + e] = v[e];
        __syncthreads();
        for (int j = k >> 1; j >= 128; j >>= 1) {
#pragma unroll
            for (int e = 0; e < 4; e++) {
                int i = tid + e * 256;
                if ((i & j) == 0) {
                    int p = i | j;
                    ull a = kv[i], b = kv[p];
                    bool asc2 = ((i & k) == 0);
                    if ((a > b) == asc2) { kv[i] = b; kv[p] = a; }
                }
            }
            __syncthreads();
        }
#pragma unroll
        for (int e = 0; e < 4; e++) v[e] = kv[i0 + e];
        const bool asc = ((i0 & k) == 0);
#pragma unroll
        for (int j = 64; j >= 4; j >>= 1) {
            const bool keepmin = (((i0 & j) == 0) == asc);
#pragma unroll
            for (int e = 0; e < 4; e++) {
                ull o = __shfl_xor_sync(0xffffffffu, v[e], j >> 2);
                ull mn = (v[e] < o) ? v[e] : o;
                ull mx = (v[e] < o) ? o : v[e];
                v[e] = keepmin ? mn : mx;
            }
        }
        cswap(v[0], v[2], asc); cswap(v[1], v[3], asc);
        cswap(v[0], v[1], asc); cswap(v[2], v[3], asc);
        __syncthreads();
    }

#pragma unroll
    for (int e = 0; e < 4; e++)
        g_sc[(head * NSC + chunk) * SC + i0 + e] = v[e];
}

// ============================================================================
// Sort stage 2 (R13 config): rank-merge of 4 chunks (3 gallops) + fused weights
// ============================================================================
__global__ void __launch_bounds__(256)
merge_kernel(int layer, int H) {
    float* ss = (layer == 0) ? g_ss1 : g_ss2;
    int*   si = (layer == 0) ? g_si1 : g_si2;
    float* w0 = (layer == 0) ? g_w0_1 : g_w0_2;
    float* w1 = (layer == 0) ? g_w1_1 : g_w1_2;

    int gid = blockIdx.x * 256 + threadIdx.x;
    if (gid >= H * NN) return;
    int head = gid >> 12;
    int i = gid & (NN - 1);
    int c = i >> 10, p = i & (SC - 1);

    const ull* base = g_sc + (size_t)head * NN;
    ull v = base[c * SC + p];

    const ull* oth[3];
    int cc = 0;
#pragma unroll
    for (int q = 0; q < 4; q++) if (q != c) oth[cc++] = base + q * SC;

    int p0 = 0, p1 = 0, p2 = 0;
#pragma unroll
    for (int step = SC; step >= 1; step >>= 1) {
        bool g0 = (p0 + step <= SC) && (__ldg(&oth[0][p0 + step - 1]) < v);
        bool g1 = (p1 + step <= SC) && (__ldg(&oth[1][p1 + step - 1]) < v);
        bool g2 = (p2 + step <= SC) && (__ldg(&oth[2][p2 + step - 1]) < v);
        if (g0) p0 += step;
        if (g1) p1 += step;
        if (g2) p2 += step;
    }
    int rank = p + p0 + p1 + p2;

    unsigned ku = (unsigned)(v >> 32);
    float f = (ku & 0x80000000u) ? __uint_as_float(ku ^ 0x80000000u)
                                 : __uint_as_float(~ku);
    ss[head * NN + rank] = f;
    si[head * NN + rank] = (int)(v & 0xffffffffu);
    w0[head * NN + rank] = expf(0.2f * f);
    w1[head * NN + rank] = expf(f);
}

// ============================================================================
// zscan: inclusive prefix (w0) / suffix (w1) scans, shfl-based
// ============================================================================
__global__ void __launch_bounds__(1024)
zscan_kernel(int layer) {
    const int dir = blockIdx.x, head = blockIdx.y;
    const float* w = (layer == 0) ? (dir == 0 ? g_w0_1 : g_w1_1)
                                  : (dir == 0 ? g_w0_2 : g_w1_2);
    float* z = (layer == 0) ? (dir == 0 ? g_z0_1 : g_z1_1)
                            : (dir == 0 ? g_z0_2 : g_z1_2);

    const int tid = threadIdx.x;
    const int lane = tid & 31, warp = tid >> 5;
    __shared__ float wsum[32], woff[32];

    const int i0 = 4 * tid;
    float4 v = *reinterpret_cast<const float4*>(&w[head * NN + i0]);

    if (dir == 0) {
        float p0 = v.x, p1 = p0 + v.y, p2 = p1 + v.z, p3 = p2 + v.w;
        float x = p3;
#pragma unroll
        for (int o = 1; o < 32; o <<= 1) {
            float y = __shfl_up_sync(0xffffffffu, x, o);
            if (lane >= o) x += y;
        }
        float wexcl = x - p3;
        if (lane == 31) wsum[warp] = x;
        __syncthreads();
        if (warp == 0) {
            float t = wsum[lane];
#pragma unroll
            for (int o = 1; o < 32; o <<= 1) {
                float y = __shfl_up_sync(0xffffffffu, t, o);
                if (lane >= o) t += y;
            }
            woff[lane] = t - wsum[lane];
        }
        __syncthreads();
        float off = woff[warp] + wexcl;
        *reinterpret_cast<float4*>(&z[head * NN + i0]) =
            make_float4(p0 + off, p1 + off, p2 + off, p3 + off);
    } else {
        float q3 = v.w, q2 = q3 + v.z, q1 = q2 + v.y, q0 = q1 + v.x;
        float x = q0;
#pragma unroll
        for (int o = 1; o < 32; o <<= 1) {
            float y = __shfl_down_sync(0xffffffffu, x, o);
            if (lane + o < 32) x += y;
        }
        float wexcl = x - q0;
        if (lane == 0) wsum[warp] = x;
        __syncthreads();
        if (warp == 0) {
            float t = wsum[lane];
#pragma unroll
            for (int o = 1; o < 32; o <<= 1) {
                float y = __shfl_down_sync(0xffffffffu, t, o);
                if (lane + o < 32) t += y;
            }
            woff[lane] = t - wsum[lane];
        }
        __syncthreads();
        float off = woff[warp] + wexcl;
        *reinterpret_cast<float4*>(&z[head * NN + i0]) =
            make_float4(q0 + off, q1 + off, q2 + off, q3 + off);
    }
}

// ============================================================================
// ksearch: split points + per-(head,node) scalar coefficients
// ============================================================================
__global__ void __launch_bounds__(256)
ksearch_kernel(int layer, int H) {
    const float* t  = (layer == 0) ? g_t1 : g_t2;
    const float* ss = (layer == 0) ? g_ss1 : g_ss2;
    const float* z0 = (layer == 0) ? g_z0_1 : g_z0_2;
    const float* z1 = (layer == 0) ? g_z1_1 : g_z1_2;
    int*    kk = (layer == 0) ? g_k1 : g_k2;
    float2* aa = (layer == 0) ? g_a1 : g_a2;

    int gid = blockIdx.x * 256 + threadIdx.x;
    if (gid >= H * NN) return;
    int head = gid >> 12;
    const float* ssh = ss + head * NN;
    float tv = t[gid];
    float tau = -tv;
    int pos = 0;
#pragma unroll
    for (int step = NN; step >= 1; step >>= 1) {
        if (pos + step <= NN && __ldg(&ssh[pos + step - 1]) <= tau) pos += step;
    }
    kk[gid] = pos;

    float z0v = (pos > 0)  ? z0[head * NN + pos - 1] : 0.f;
    float z1v = (pos < NN) ? z1[head * NN + pos]     : 0.f;
    float et  = expf(tv);
    float et2 = expf(0.2f * tv);
    float inv = 1.f / (et * z1v + et2 * z0v);
    float a0 = (pos > 0)  ? et2 * inv : 0.f;
    float a1 = (pos < NN) ? et  * inv : 0.f;
    aa[gid] = make_float2(a0, a1);
}

// ============================================================================
// passA: chunked vector scans (MLP=16 gathers)
// ============================================================================
__global__ void __launch_bounds__(CD)
passA_kernel(int layer, int F) {
    const float* h  = (layer == 0) ? g_h1 : g_h2;
    const int*   si = (layer == 0) ? g_si1 : g_si2;
    const float* w0 = (layer == 0) ? g_w0_1 : g_w0_2;
    const float* w1 = (layer == 0) ? g_w1_1 : g_w1_2;
    float* I0 = (layer == 0) ? g_I0_1 : g_I0_2;
    float* S1 = (layer == 0) ? g_S1_1 : g_S1_2;

    const int chunk = blockIdx.x, head = blockIdx.y, dir = blockIdx.z;
    const int c = threadIdx.x;
    const int base = head * NN + chunk * CHUNK;

    __shared__ int   sj[CHUNK];
    __shared__ float sw[CHUNK];
    const float* wsel = (dir == 0) ? w0 : w1;
    for (int r = threadIdx.x; r < CHUNK; r += blockDim.x) {
        sj[r] = si[base + r] * F + head * CD;
        sw[r] = wsel[base + r];
    }
    __syncthreads();

    float acc = 0.f;
    if (dir == 0) {
        float* dst = I0 + (size_t)base * CD + c;
        for (int rr = 0; rr < CHUNK; rr += 16) {
            float v[16];
#pragma unroll
            for (int u = 0; u < 16; u++) v[u] = __ldg(&h[sj[rr + u] + c]);
#pragma unroll
            for (int u = 0; u < 16; u++) {
                acc = fmaf(sw[rr + u], v[u], acc);
                dst[(size_t)(rr + u) * CD] = acc;
            }
        }
    } else {
        float* dst = S1 + (size_t)base * CD + c;
        for (int rr = CHUNK - 16; rr >= 0; rr -= 16) {
            float v[16];
#pragma unroll
            for (int u = 15; u >= 0; u--) v[u] = __ldg(&h[sj[rr + u] + c]);
#pragma unroll
            for (int u = 15; u >= 0; u--) {
                acc = fmaf(sw[rr + u], v[u], acc);
                dst[(size_t)(rr + u) * CD] = acc;
            }
        }
    }
}

// ---------------- cross-chunk offsets ----------------
__global__ void passB_kernel(int layer) {
    const float* I0 = (layer == 0) ? g_I0_1 : g_I0_2;
    const float* S1 = (layer == 0) ? g_S1_1 : g_S1_2;
    float* O0 = (layer == 0) ? g_O0_1 : g_O0_2;
    float* O1 = (layer == 0) ? g_O1_1 : g_O1_2;

    int head = blockIdx.x, c = threadIdx.x;
    float acc = 0.f;
    for (int ch = 0; ch < NCH; ch++) {
        O0[(head * NCH + ch) * CD + c] = acc;
        acc += I0[(head * NN + ch * CHUNK + CHUNK - 1) * CD + c];
    }
    acc = 0.f;
    for (int ch = NCH - 1; ch >= 0; ch--) {
        O1[(head * NCH + ch) * CD + c] = acc;
        acc += S1[(head * NN + ch * CHUNK) * CD + c];
    }
}

// ---------------- lookup: 2 clamped table reads + 2 FMA + elu ----------------
// Layer 0 writes x1 directly as split bf16 (feeds mma GEMM2); layer 1 writes fp32.
__global__ void __launch_bounds__(CD)
lookup_kernel(int layer, const float* __restrict__ bias, int F) {
    const int*    kk = (layer == 0) ? g_k1 : g_k2;
    const float2* aa = (layer == 0) ? g_a1 : g_a2;
    const float* I0 = (layer == 0) ? g_I0_1 : g_I0_2;
    const float* S1 = (layer == 0) ? g_S1_1 : g_S1_2;
    const float* O0 = (layer == 0) ? g_O0_1 : g_O0_2;
    const float* O1 = (layer == 0) ? g_O1_1 : g_O1_2;

    int head = blockIdx.y, c = threadIdx.x;
    float bv = bias[head * CD + c];

#pragma unroll 2
    for (int u = 0; u < 8; u++) {
        int i = blockIdx.x * 8 + u;
        int k = kk[head * NN + i];
        float2 a = aa[head * NN + i];

        int k0i = (k > 0) ? (k - 1) : 0;
        int k1i = (k < NN) ? k : (NN - 1);
        float A0 = I0[(size_t)(head * NN + k0i) * CD + c] +
                   O0[(head * NCH + k0i / CHUNK) * CD + c];
        float A1 = S1[(size_t)(head * NN + k1i) * CD + c] +
                   O1[(head * NCH + k1i / CHUNK) * CD + c];
        float o = fmaf(a.y, A1, fmaf(a.x, A0, bv));
        float x = elu1(o);
        size_t idx = (size_t)i * F + head * CD + c;
        if (layer == 0) {
            __nv_bfloat16 hh = __float2bfloat16(x);
            g_x1H[idx] = hh;
            g_x1L[idx] = __float2bfloat16(x - __bfloat162float(hh));
        } else {
            g_x2[idx] = x;
        }
    }
}

// ---------------- column mean + FC ----------------
__global__ void colpart_kernel() {
    int b = blockIdx.x, c = threadIdx.x;
    float acc = 0.f;
    for (int r = 0; r < NN / 32; r++) acc += g_x2[(b * (NN / 32) + r) * CD + c];
    g_part[b * CD + c] = acc;
}
__global__ void __launch_bounds__(DIN)
colfinal_fc_kernel(const float* __restrict__ fcW, const float* __restrict__ fcb,
                   float* __restrict__ out) {
    __shared__ float m[CD];
    int tid = threadIdx.x;
    if (tid < CD) {
        float a = 0.f;
        for (int b = 0; b < 32; b++) a += g_part[b * CD + tid];
        m[tid] = a * (1.f / (float)NN);
    }
    __syncthreads();
    if (tid < DIN) {
        float acc = fcb[tid];
#pragma unroll 8
        for (int c = 0; c < CD; c++) acc = fmaf(m[c], fcW[c * DIN + tid], acc);
        out[tid] = acc;
    }
}

// ---------------- launch ----------------
extern "C" void kernel_launch(void* const* d_in, const int* in_sizes, int n_in,
                              void* d_out, int out_size) {
    const float* X   = (const float*)d_in[0];
    const float* W1  = (const float*)d_in[1];
    const float* as1 = (const float*)d_in[2];
    const float* ad1 = (const float*)d_in[3];
    const float* b1  = (const float*)d_in[4];
    const float* W2  = (const float*)d_in[5];
    const float* as2 = (const float*)d_in[6];
    const float* ad2 = (const float*)d_in[7];
    const float* b2  = (const float*)d_in[8];
    const float* fcW = (const float*)d_in[9];
    const float* fcb = (const float*)d_in[10];
    float* out = (float*)d_out;

    const int MMA_SMEM = 2 * 4 * TILEB;   // 81920 bytes
    cudaFuncSetAttribute(gemm_mma_kernel,
                         cudaFuncAttributeMaxDynamicSharedMemorySize, MMA_SMEM);

    // conv kernels first (keeps launch #4 = layer-0 GEMM for ncu capture)
    convA_kernel<<<(NN * DIN / 4) / 256, 256>>>(X);
    convB_kernel<<<dim3(DIN / 32, F1 / 32), 256>>>(W1, 0);
    convB_kernel<<<dim3(F1 / 32, CD / 32), 256>>>(W2, 1);

    // Layer 1: split-bf16 mma.sync GEMM (M=4096, K=768, N=512)
    gemm_mma_kernel<<<dim3(NN / 128, HH1), 512, MMA_SMEM>>>(0, as1, ad1);
    sortchunk_kernel<<<dim3(NSC, HH1), 256>>>(0);
    merge_kernel<<<(HH1 * NN) / 256, 256>>>(0, HH1);
    zscan_kernel<<<dim3(2, HH1), 1024>>>(0);
    ksearch_kernel<<<(HH1 * NN) / 256, 256>>>(0, HH1);
    passA_kernel<<<dim3(NCH, HH1, 2), CD>>>(0, F1);
    passB_kernel<<<HH1, CD>>>(0);
    lookup_kernel<<<dim3(NN / 8, HH1), CD>>>(0, b1, F1);

    // Layer 2: split-bf16 mma.sync GEMM (M=4096, K=512, N=128)
    gemm_mma_kernel<<<dim3(NN / 128, 1), 512, MMA_SMEM>>>(1, as2, ad2);
    sortchunk_kernel<<<dim3(NSC, 1), 256>>>(1);
    merge_kernel<<<NN / 256, 256>>>(1, 1);
    zscan_kernel<<<dim3(2, 1), 1024>>>(1);
    ksearch_kernel<<<NN / 256, 256>>>(1, 1);
    passA_kernel<<<dim3(NCH, 1, 2), CD>>>(1, CD);
    passB_kernel<<<1, CD>>>(1);
    lookup_kernel<<<dim3(NN / 8, 1), CD>>>(1, b2, CD);

    // Mean + FC
    colpart_kernel<<<32, CD>>>();
    colfinal_fc_kernel<<<1, DIN>>>(fcW, fcb, out);
}